// round 10
// baseline (speedup 1.0000x reference)
#include <cuda_runtime.h>
#include <cuda_bf16.h>
#include <math_constants.h>

// Sliding-window causal attention, B=1 H=8 SQ=SK=4096 D=64, window=1024, block=64.
// mma.sync.m16n8k16 bf16x3 flash attention, double-buffered cp.async pipeline,
// persistent CTAs with dynamic (atomic) tile scheduling for load balance.

#define Hn   8
#define SQn  4096
#define Dn   64
#define NTILES 512

typedef unsigned int u32;

// ---- bf16 hi/lo scratch (device globals; no runtime allocation) ----
__device__ __nv_bfloat16 g_Kh[Hn * SQn * Dn];
__device__ __nv_bfloat16 g_Kl[Hn * SQn * Dn];
__device__ __nv_bfloat16 g_Vth[Hn * Dn * SQn];   // transposed: [h][d][tok]
__device__ __nv_bfloat16 g_Vtl[Hn * Dn * SQn];
__device__ u32 g_tile_ctr;

// ============================ helpers ============================
__device__ __forceinline__ u32 smem_u32(const void* p) {
    u32 a;
    asm("{ .reg .u64 t; cvta.to.shared.u64 t, %1; cvt.u32.u64 %0, t; }"
        : "=r"(a) : "l"(p));
    return a;
}
__device__ __forceinline__ float ex2f(float x) {
    float y; asm("ex2.approx.ftz.f32 %0, %1;" : "=f"(y) : "f"(x)); return y;
}
// pack {lo=a, hi=b} as bf16x2
__device__ __forceinline__ u32 cvt2(float a, float b) {
    u32 r; asm("cvt.rn.bf16x2.f32 %0, %1, %2;" : "=r"(r) : "f"(b), "f"(a));
    return r;
}
// split pair (a,b) into bf16 hi pair + bf16 residual pair
__device__ __forceinline__ void split2(float a, float b, u32& hi, u32& lo) {
    hi = cvt2(a, b);
    float ah = __uint_as_float(hi << 16);
    float bh = __uint_as_float(hi & 0xFFFF0000u);
    lo = cvt2(a - ah, b - bh);
}
__device__ __forceinline__ void ldsm4(u32& r0, u32& r1, u32& r2, u32& r3, u32 a) {
    asm volatile("ldmatrix.sync.aligned.m8n8.x4.shared.b16 {%0,%1,%2,%3}, [%4];"
                 : "=r"(r0), "=r"(r1), "=r"(r2), "=r"(r3) : "r"(a));
}
__device__ __forceinline__ void mma16816(float* c, const u32* a, u32 b0, u32 b1) {
    asm volatile(
        "mma.sync.aligned.m16n8k16.row.col.f32.bf16.bf16.f32 "
        "{%0,%1,%2,%3}, {%4,%5,%6,%7}, {%8,%9}, {%0,%1,%2,%3};"
        : "+f"(c[0]), "+f"(c[1]), "+f"(c[2]), "+f"(c[3])
        : "r"(a[0]), "r"(a[1]), "r"(a[2]), "r"(a[3]), "r"(b0), "r"(b1));
}
__device__ __forceinline__ void cp16(u32 dst, const void* src) {
    asm volatile("cp.async.cg.shared.global [%0], [%1], 16;"
                 :: "r"(dst), "l"(src) : "memory");
}
__device__ __forceinline__ void cp_commit() {
    asm volatile("cp.async.commit_group;" ::: "memory");
}
__device__ __forceinline__ void cp_wait0() {
    asm volatile("cp.async.wait_group 0;" ::: "memory");
}
// swizzled tile offset: 64 rows x 8 chunks of 16B; chunk ^= row&7 (ldmatrix conflict-free)
__device__ __forceinline__ u32 swz(int r, int c) {
    return (u32)(r * 128 + ((c ^ (r & 7)) * 16));
}

// Buffer layout (per buffer, 32768 B): Kh @0, Kl @8192, Vh @16384, Vl @24576
#define KH_OFF 0
#define KL_OFF 8192
#define VH_OFF 16384
#define VL_OFF 24576
#define BUF_BYTES 32768
#define SMEM_TOTAL (2 * BUF_BYTES)

// Issue the 4-tile cp.async fill for (h, kb) into buffer at smem addr `base`.
__device__ __forceinline__ void fill_tiles(u32 base, int h, int kb, int t) {
    const __nv_bfloat16* srcKh = g_Kh  + ((size_t)(h * SQn + kb * 64)) * Dn;
    const __nv_bfloat16* srcKl = g_Kl  + ((size_t)(h * SQn + kb * 64)) * Dn;
    const __nv_bfloat16* srcVh = g_Vth + (size_t)h * Dn * SQn + kb * 64;
    const __nv_bfloat16* srcVl = g_Vtl + (size_t)h * Dn * SQn + kb * 64;
#pragma unroll
    for (int i = 0; i < 4; i++) {
        int idx = t + i * 128;
        int r = idx >> 3, c = idx & 7;
        u32 off = swz(r, c);
        cp16(base + KH_OFF + off, srcKh + (size_t)r * Dn  + c * 8);
        cp16(base + KL_OFF + off, srcKl + (size_t)r * Dn  + c * 8);
        cp16(base + VH_OFF + off, srcVh + (size_t)r * SQn + c * 8);
        cp16(base + VL_OFF + off, srcVl + (size_t)r * SQn + c * 8);
    }
    cp_commit();
}

// ====================== counter reset ======================
__global__ void reset_ctr_kernel() { g_tile_ctr = 0u; }

// ====================== pre-conversion kernel ======================
__global__ void __launch_bounds__(256)
prep_kernel(const float* __restrict__ K, const float* __restrict__ V) {
    __shared__ float sv[64 * 65];
    const int h = blockIdx.y, tb = blockIdx.x, t = threadIdx.x;
    const float* Ks = K + ((size_t)(h * SQn + tb * 64)) * Dn;
    const float* Vs = V + ((size_t)(h * SQn + tb * 64)) * Dn;
#pragma unroll
    for (int i = 0; i < 16; i++) {
        int e = t + i * 256;             // 0..4095
        int tok = e >> 6, d = e & 63;
        float kv = Ks[e];
        __nv_bfloat16 kh = __float2bfloat16(kv);
        size_t o = (size_t)(h * SQn + tb * 64 + tok) * Dn + d;
        g_Kh[o] = kh;
        g_Kl[o] = __float2bfloat16(kv - __bfloat162float(kh));
        sv[d * 65 + tok] = Vs[e];
    }
    __syncthreads();
#pragma unroll
    for (int i = 0; i < 16; i++) {
        int e = t + i * 256;
        int d = e >> 6, tl = e & 63;
        float vv = sv[d * 65 + tl];
        __nv_bfloat16 vh = __float2bfloat16(vv);
        size_t o = (size_t)(h * Dn + d) * SQn + tb * 64 + tl;
        g_Vth[o] = vh;
        g_Vtl[o] = __float2bfloat16(vv - __bfloat162float(vh));
    }
}

// ========================= main kernel (persistent) =========================
__global__ void __launch_bounds__(128, 3)
swa_mma_kernel(const float* __restrict__ Qg, float* __restrict__ Og)
{
    extern __shared__ __align__(128) char dynsm[];
    __shared__ u32 s_idx_sh;
    const u32 sbase = smem_u32(dynsm);

    const int t    = threadIdx.x;
    const int lane = t & 31;
    const int w    = t >> 5;
    const int gid  = lane >> 2;
    const int tig  = lane & 3;
    const int sub  = lane >> 3, wi = lane & 7;
    const int brow0 = (sub >> 1) * 8 + wi;   // + jp*16
    const int bchb  = sub & 1;               // + 2*ks

    for (;;) {
        __syncthreads();     // previous tile's smem reads complete
        if (t == 0) s_idx_sh = atomicAdd(&g_tile_ctr, 1u);
        __syncthreads();
        const u32 idx = s_idx_sh;
        if (idx >= NTILES) break;

        const int qb = 63 - (int)(idx >> 3);   // heavy q-blocks first
        const int h  = (int)(idx & 7);
        const int Q0 = qb * 64;

        int kb_lo = qb - 15; if (kb_lo < 0) kb_lo = 0;

        // ---- prefetch first K/V tile into buffer 0 (overlaps Q staging) ----
        fill_tiles(sbase, h, kb_lo, t);

        // ---- stage Q (scaled, bf16 hi/lo, swizzled) into buffer 1 ----
        {
            const float SC = 0.125f * 1.4426950408889634f;   // d^-1/2 * log2(e)
            const int r   = t >> 1;
            const int ch0 = (t & 1) * 4;
            const float* qrow = Qg + ((size_t)(h * SQn + Q0 + r)) * Dn + ch0 * 8;
            char* qbh = dynsm + BUF_BYTES + KH_OFF;
            char* qbl = dynsm + BUF_BYTES + KL_OFF;
#pragma unroll
            for (int c = 0; c < 4; c++) {
                float4 f0 = *(const float4*)(qrow + c * 8);
                float4 f1 = *(const float4*)(qrow + c * 8 + 4);
                u32 h0, l0, h1, l1, h2, l2, h3, l3;
                split2(f0.x * SC, f0.y * SC, h0, l0);
                split2(f0.z * SC, f0.w * SC, h1, l1);
                split2(f1.x * SC, f1.y * SC, h2, l2);
                split2(f1.z * SC, f1.w * SC, h3, l3);
                u32 off = swz(r, ch0 + c);
                *(uint4*)(qbh + off) = make_uint4(h0, h1, h2, h3);
                *(uint4*)(qbl + off) = make_uint4(l0, l1, l2, l3);
            }
        }
        __syncthreads();

        // ---- Q fragments (A-layout) for 4 k-steps, hi+lo ----
        u32 qh[4][4], ql[4][4];
        {
            const int row = w * 16 + (sub & 1) * 8 + wi;
            const int chb = sub >> 1;
            const u32 qbh = sbase + BUF_BYTES + KH_OFF;
            const u32 qbl = sbase + BUF_BYTES + KL_OFF;
#pragma unroll
            for (int ks = 0; ks < 4; ks++) {
                ldsm4(qh[ks][0], qh[ks][1], qh[ks][2], qh[ks][3], qbh + swz(row, 2 * ks + chb));
                ldsm4(ql[ks][0], ql[ks][1], ql[ks][2], ql[ks][3], qbl + swz(row, 2 * ks + chb));
            }
        }

        float O[8][4];
#pragma unroll
        for (int j = 0; j < 8; j++)
#pragma unroll
            for (int e = 0; e < 4; e++) O[j][e] = 0.f;
        float m0 = -1e30f, m1 = -1e30f, l0 = 0.f, l1 = 0.f;

        for (int kb = kb_lo; kb <= qb; kb++) {
            const u32 base = sbase + (u32)(((kb - kb_lo) & 1) * BUF_BYTES);

            cp_wait0();          // tile kb landed (this thread's copies)
            __syncthreads();     // all threads' copies visible; prev buffer free

            if (kb < qb)         // prefetch next tile into the other buffer
                fill_tiles(sbase + (u32)(((kb - kb_lo + 1) & 1) * BUF_BYTES), h, kb + 1, t);

            const u32 bKh = base + KH_OFF, bKl = base + KL_OFF;
            const u32 bVh = base + VH_OFF, bVl = base + VL_OFF;

            // ---- S = Q K^T, 3-term bf16 split ----
            float S[8][4];
#pragma unroll
            for (int j = 0; j < 8; j++)
#pragma unroll
                for (int e = 0; e < 4; e++) S[j][e] = 0.f;

#pragma unroll
            for (int ks = 0; ks < 4; ks++) {
#pragma unroll
                for (int jp = 0; jp < 4; jp++) {
                    u32 kb0, kb1, kb2, kb3, kc0, kc1, kc2, kc3;
                    u32 off = swz(jp * 16 + brow0, 2 * ks + bchb);
                    ldsm4(kb0, kb1, kb2, kb3, bKh + off);
                    ldsm4(kc0, kc1, kc2, kc3, bKl + off);
                    mma16816(S[2 * jp],     qh[ks], kb0, kb1);
                    mma16816(S[2 * jp],     qh[ks], kc0, kc1);
                    mma16816(S[2 * jp],     ql[ks], kb0, kb1);
                    mma16816(S[2 * jp + 1], qh[ks], kb2, kb3);
                    mma16816(S[2 * jp + 1], qh[ks], kc2, kc3);
                    mma16816(S[2 * jp + 1], ql[ks], kb2, kb3);
                }
            }

            // ---- causal mask on diagonal block ----
            if (kb == qb) {
                const int rl0 = w * 16 + gid;
                const int rl1 = rl0 + 8;
#pragma unroll
                for (int j = 0; j < 8; j++) {
#pragma unroll
                    for (int e = 0; e < 2; e++) {
                        int col = 8 * j + 2 * tig + e;
                        if (col > rl0) S[j][e]     = -CUDART_INF_F;
                        if (col > rl1) S[j][2 + e] = -CUDART_INF_F;
                    }
                }
            }

            // ---- online softmax (rows gid, gid+8; 4 lanes per row) ----
            float mx0 = S[0][0], mx1 = S[0][2];
#pragma unroll
            for (int j = 0; j < 8; j++) {
                mx0 = fmaxf(mx0, fmaxf(S[j][0], S[j][1]));
                mx1 = fmaxf(mx1, fmaxf(S[j][2], S[j][3]));
            }
            mx0 = fmaxf(mx0, __shfl_xor_sync(0xffffffffu, mx0, 1));
            mx0 = fmaxf(mx0, __shfl_xor_sync(0xffffffffu, mx0, 2));
            mx1 = fmaxf(mx1, __shfl_xor_sync(0xffffffffu, mx1, 1));
            mx1 = fmaxf(mx1, __shfl_xor_sync(0xffffffffu, mx1, 2));
            const float mn0 = fmaxf(m0, mx0), mn1 = fmaxf(m1, mx1);
            const float corr0 = ex2f(m0 - mn0), corr1 = ex2f(m1 - mn1);
            m0 = mn0; m1 = mn1;
            float rs0 = 0.f, rs1 = 0.f;
#pragma unroll
            for (int j = 0; j < 8; j++) {
                S[j][0] = ex2f(S[j][0] - mn0); rs0 += S[j][0];
                S[j][1] = ex2f(S[j][1] - mn0); rs0 += S[j][1];
                S[j][2] = ex2f(S[j][2] - mn1); rs1 += S[j][2];
                S[j][3] = ex2f(S[j][3] - mn1); rs1 += S[j][3];
            }
            rs0 += __shfl_xor_sync(0xffffffffu, rs0, 1);
            rs0 += __shfl_xor_sync(0xffffffffu, rs0, 2);
            rs1 += __shfl_xor_sync(0xffffffffu, rs1, 1);
            rs1 += __shfl_xor_sync(0xffffffffu, rs1, 2);
            l0 = l0 * corr0 + rs0;
            l1 = l1 * corr1 + rs1;
#pragma unroll
            for (int j = 0; j < 8; j++) {
                O[j][0] *= corr0; O[j][1] *= corr0;
                O[j][2] *= corr1; O[j][3] *= corr1;
            }

            // ---- O += P V, 3-term bf16 split; P frags straight from S regs ----
#pragma unroll
            for (int ks = 0; ks < 4; ks++) {
                u32 ah[4], al[4];
                split2(S[2 * ks][0],     S[2 * ks][1],     ah[0], al[0]);
                split2(S[2 * ks][2],     S[2 * ks][3],     ah[1], al[1]);
                split2(S[2 * ks + 1][0], S[2 * ks + 1][1], ah[2], al[2]);
                split2(S[2 * ks + 1][2], S[2 * ks + 1][3], ah[3], al[3]);
#pragma unroll
                for (int jp = 0; jp < 4; jp++) {
                    u32 vb0, vb1, vb2, vb3, vc0, vc1, vc2, vc3;
                    u32 off = swz(jp * 16 + brow0, 2 * ks + bchb);
                    ldsm4(vb0, vb1, vb2, vb3, bVh + off);
                    ldsm4(vc0, vc1, vc2, vc3, bVl + off);
                    mma16816(O[2 * jp],     ah, vb0, vb1);
                    mma16816(O[2 * jp],     ah, vc0, vc1);
                    mma16816(O[2 * jp],     al, vb0, vb1);
                    mma16816(O[2 * jp + 1], ah, vb2, vb3);
                    mma16816(O[2 * jp + 1], ah, vc2, vc3);
                    mma16816(O[2 * jp + 1], al, vb2, vb3);
                }
            }
        }

        // ---- epilogue: normalize + store ----
        const float inv0 = 1.0f / l0;
        const float inv1 = 1.0f / l1;
        const size_t g0 = (size_t)(h * SQn + Q0 + w * 16 + gid) * Dn;
        const size_t g1 = g0 + (size_t)8 * Dn;
#pragma unroll
        for (int j = 0; j < 8; j++) {
            int col = 8 * j + 2 * tig;
            *(float2*)(Og + g0 + col) = make_float2(O[j][0] * inv0, O[j][1] * inv0);
            *(float2*)(Og + g1 + col) = make_float2(O[j][2] * inv1, O[j][3] * inv1);
        }
    }
}

extern "C" void kernel_launch(void* const* d_in, const int* in_sizes, int n_in,
                              void* d_out, int out_size)
{
    (void)in_sizes; (void)n_in; (void)out_size;
    const float* q = (const float*)d_in[0];
    const float* k = (const float*)d_in[1];
    const float* v = (const float*)d_in[2];
    float* o = (float*)d_out;

    cudaFuncSetAttribute(swa_mma_kernel,
                         cudaFuncAttributeMaxDynamicSharedMemorySize, SMEM_TOTAL);
    reset_ctr_kernel<<<1, 1>>>();
    prep_kernel<<<dim3(64, Hn), 256>>>(k, v);
    swa_mma_kernel<<<444, 128, SMEM_TOTAL>>>(q, o);
}

// round 11
// speedup vs baseline: 1.0004x; 1.0004x over previous
#include <cuda_runtime.h>
#include <cuda_bf16.h>
#include <math_constants.h>

// Sliding-window causal attention, B=1 H=8 SQ=SK=4096 D=64, window=1024, block=64.
// mma.sync.m16n8k16 bf16x3 flash attention, double-buffered cp.async pipeline,
// persistent CTAs with dynamic (atomic) tile scheduling for load balance.

#define Hn   8
#define SQn  4096
#define Dn   64
#define NTILES 512

typedef unsigned int u32;

// ---- bf16 hi/lo scratch (device globals; no runtime allocation) ----
__device__ __nv_bfloat16 g_Kh[Hn * SQn * Dn];
__device__ __nv_bfloat16 g_Kl[Hn * SQn * Dn];
__device__ __nv_bfloat16 g_Vth[Hn * Dn * SQn];   // transposed: [h][d][tok]
__device__ __nv_bfloat16 g_Vtl[Hn * Dn * SQn];
__device__ u32 g_tile_ctr;

// ============================ helpers ============================
__device__ __forceinline__ u32 smem_u32(const void* p) {
    u32 a;
    asm("{ .reg .u64 t; cvta.to.shared.u64 t, %1; cvt.u32.u64 %0, t; }"
        : "=r"(a) : "l"(p));
    return a;
}
__device__ __forceinline__ float ex2f(float x) {
    float y; asm("ex2.approx.ftz.f32 %0, %1;" : "=f"(y) : "f"(x)); return y;
}
// pack {lo=a, hi=b} as bf16x2
__device__ __forceinline__ u32 cvt2(float a, float b) {
    u32 r; asm("cvt.rn.bf16x2.f32 %0, %1, %2;" : "=r"(r) : "f"(b), "f"(a));
    return r;
}
// split pair (a,b) into bf16 hi pair + bf16 residual pair
__device__ __forceinline__ void split2(float a, float b, u32& hi, u32& lo) {
    hi = cvt2(a, b);
    float ah = __uint_as_float(hi << 16);
    float bh = __uint_as_float(hi & 0xFFFF0000u);
    lo = cvt2(a - ah, b - bh);
}
__device__ __forceinline__ void ldsm4(u32& r0, u32& r1, u32& r2, u32& r3, u32 a) {
    asm volatile("ldmatrix.sync.aligned.m8n8.x4.shared.b16 {%0,%1,%2,%3}, [%4];"
                 : "=r"(r0), "=r"(r1), "=r"(r2), "=r"(r3) : "r"(a));
}
__device__ __forceinline__ void mma16816(float* c, const u32* a, u32 b0, u32 b1) {
    asm volatile(
        "mma.sync.aligned.m16n8k16.row.col.f32.bf16.bf16.f32 "
        "{%0,%1,%2,%3}, {%4,%5,%6,%7}, {%8,%9}, {%0,%1,%2,%3};"
        : "+f"(c[0]), "+f"(c[1]), "+f"(c[2]), "+f"(c[3])
        : "r"(a[0]), "r"(a[1]), "r"(a[2]), "r"(a[3]), "r"(b0), "r"(b1));
}
__device__ __forceinline__ void cp16(u32 dst, const void* src) {
    asm volatile("cp.async.cg.shared.global [%0], [%1], 16;"
                 :: "r"(dst), "l"(src) : "memory");
}
__device__ __forceinline__ void cp_commit() {
    asm volatile("cp.async.commit_group;" ::: "memory");
}
__device__ __forceinline__ void cp_wait0() {
    asm volatile("cp.async.wait_group 0;" ::: "memory");
}
// swizzled tile offset: 64 rows x 8 chunks of 16B; chunk ^= row&7 (ldmatrix conflict-free)
__device__ __forceinline__ u32 swz(int r, int c) {
    return (u32)(r * 128 + ((c ^ (r & 7)) * 16));
}

// Buffer layout (per buffer, 32768 B): Kh @0, Kl @8192, Vh @16384, Vl @24576
#define KH_OFF 0
#define KL_OFF 8192
#define VH_OFF 16384
#define VL_OFF 24576
#define BUF_BYTES 32768
#define SMEM_TOTAL (2 * BUF_BYTES)

// Issue the 4-tile cp.async fill for (h, kb) into buffer at smem addr `base`.
__device__ __forceinline__ void fill_tiles(u32 base, int h, int kb, int t) {
    const __nv_bfloat16* srcKh = g_Kh  + ((size_t)(h * SQn + kb * 64)) * Dn;
    const __nv_bfloat16* srcKl = g_Kl  + ((size_t)(h * SQn + kb * 64)) * Dn;
    const __nv_bfloat16* srcVh = g_Vth + (size_t)h * Dn * SQn + kb * 64;
    const __nv_bfloat16* srcVl = g_Vtl + (size_t)h * Dn * SQn + kb * 64;
#pragma unroll
    for (int i = 0; i < 4; i++) {
        int idx = t + i * 128;
        int r = idx >> 3, c = idx & 7;
        u32 off = swz(r, c);
        cp16(base + KH_OFF + off, srcKh + (size_t)r * Dn  + c * 8);
        cp16(base + KL_OFF + off, srcKl + (size_t)r * Dn  + c * 8);
        cp16(base + VH_OFF + off, srcVh + (size_t)r * SQn + c * 8);
        cp16(base + VL_OFF + off, srcVl + (size_t)r * SQn + c * 8);
    }
    cp_commit();
}

// ====================== counter reset ======================
__global__ void reset_ctr_kernel() { g_tile_ctr = 0u; }

// ====================== pre-conversion kernel ======================
__global__ void __launch_bounds__(256)
prep_kernel(const float* __restrict__ K, const float* __restrict__ V) {
    __shared__ float sv[64 * 65];
    const int h = blockIdx.y, tb = blockIdx.x, t = threadIdx.x;
    const float* Ks = K + ((size_t)(h * SQn + tb * 64)) * Dn;
    const float* Vs = V + ((size_t)(h * SQn + tb * 64)) * Dn;
#pragma unroll
    for (int i = 0; i < 16; i++) {
        int e = t + i * 256;             // 0..4095
        int tok = e >> 6, d = e & 63;
        float kv = Ks[e];
        __nv_bfloat16 kh = __float2bfloat16(kv);
        size_t o = (size_t)(h * SQn + tb * 64 + tok) * Dn + d;
        g_Kh[o] = kh;
        g_Kl[o] = __float2bfloat16(kv - __bfloat162float(kh));
        sv[d * 65 + tok] = Vs[e];
    }
    __syncthreads();
#pragma unroll
    for (int i = 0; i < 16; i++) {
        int e = t + i * 256;
        int d = e >> 6, tl = e & 63;
        float vv = sv[d * 65 + tl];
        __nv_bfloat16 vh = __float2bfloat16(vv);
        size_t o = (size_t)(h * Dn + d) * SQn + tb * 64 + tl;
        g_Vth[o] = vh;
        g_Vtl[o] = __float2bfloat16(vv - __bfloat162float(vh));
    }
}

// ========================= main kernel (persistent) =========================
__global__ void __launch_bounds__(128, 3)
swa_mma_kernel(const float* __restrict__ Qg, float* __restrict__ Og)
{
    extern __shared__ __align__(128) char dynsm[];
    __shared__ u32 s_idx_sh;
    const u32 sbase = smem_u32(dynsm);

    const int t    = threadIdx.x;
    const int lane = t & 31;
    const int w    = t >> 5;
    const int gid  = lane >> 2;
    const int tig  = lane & 3;
    const int sub  = lane >> 3, wi = lane & 7;
    const int brow0 = (sub >> 1) * 8 + wi;   // + jp*16
    const int bchb  = sub & 1;               // + 2*ks

    for (;;) {
        __syncthreads();     // previous tile's smem reads complete
        if (t == 0) s_idx_sh = atomicAdd(&g_tile_ctr, 1u);
        __syncthreads();
        const u32 idx = s_idx_sh;
        if (idx >= NTILES) break;

        const int qb = 63 - (int)(idx >> 3);   // heavy q-blocks first
        const int h  = (int)(idx & 7);
        const int Q0 = qb * 64;

        int kb_lo = qb - 15; if (kb_lo < 0) kb_lo = 0;

        // ---- prefetch first K/V tile into buffer 0 (overlaps Q staging) ----
        fill_tiles(sbase, h, kb_lo, t);

        // ---- stage Q (scaled, bf16 hi/lo, swizzled) into buffer 1 ----
        {
            const float SC = 0.125f * 1.4426950408889634f;   // d^-1/2 * log2(e)
            const int r   = t >> 1;
            const int ch0 = (t & 1) * 4;
            const float* qrow = Qg + ((size_t)(h * SQn + Q0 + r)) * Dn + ch0 * 8;
            char* qbh = dynsm + BUF_BYTES + KH_OFF;
            char* qbl = dynsm + BUF_BYTES + KL_OFF;
#pragma unroll
            for (int c = 0; c < 4; c++) {
                float4 f0 = *(const float4*)(qrow + c * 8);
                float4 f1 = *(const float4*)(qrow + c * 8 + 4);
                u32 h0, l0, h1, l1, h2, l2, h3, l3;
                split2(f0.x * SC, f0.y * SC, h0, l0);
                split2(f0.z * SC, f0.w * SC, h1, l1);
                split2(f1.x * SC, f1.y * SC, h2, l2);
                split2(f1.z * SC, f1.w * SC, h3, l3);
                u32 off = swz(r, ch0 + c);
                *(uint4*)(qbh + off) = make_uint4(h0, h1, h2, h3);
                *(uint4*)(qbl + off) = make_uint4(l0, l1, l2, l3);
            }
        }
        __syncthreads();

        // ---- Q fragments (A-layout) for 4 k-steps, hi+lo ----
        u32 qh[4][4], ql[4][4];
        {
            const int row = w * 16 + (sub & 1) * 8 + wi;
            const int chb = sub >> 1;
            const u32 qbh = sbase + BUF_BYTES + KH_OFF;
            const u32 qbl = sbase + BUF_BYTES + KL_OFF;
#pragma unroll
            for (int ks = 0; ks < 4; ks++) {
                ldsm4(qh[ks][0], qh[ks][1], qh[ks][2], qh[ks][3], qbh + swz(row, 2 * ks + chb));
                ldsm4(ql[ks][0], ql[ks][1], ql[ks][2], ql[ks][3], qbl + swz(row, 2 * ks + chb));
            }
        }

        float O[8][4];
#pragma unroll
        for (int j = 0; j < 8; j++)
#pragma unroll
            for (int e = 0; e < 4; e++) O[j][e] = 0.f;
        float m0 = -1e30f, m1 = -1e30f, l0 = 0.f, l1 = 0.f;

        for (int kb = kb_lo; kb <= qb; kb++) {
            const u32 base = sbase + (u32)(((kb - kb_lo) & 1) * BUF_BYTES);

            cp_wait0();          // tile kb landed (this thread's copies)
            __syncthreads();     // all threads' copies visible; prev buffer free

            if (kb < qb)         // prefetch next tile into the other buffer
                fill_tiles(sbase + (u32)(((kb - kb_lo + 1) & 1) * BUF_BYTES), h, kb + 1, t);

            const u32 bKh = base + KH_OFF, bKl = base + KL_OFF;
            const u32 bVh = base + VH_OFF, bVl = base + VL_OFF;

            // ---- S = Q K^T, 3-term bf16 split ----
            float S[8][4];
#pragma unroll
            for (int j = 0; j < 8; j++)
#pragma unroll
                for (int e = 0; e < 4; e++) S[j][e] = 0.f;

#pragma unroll
            for (int ks = 0; ks < 4; ks++) {
#pragma unroll
                for (int jp = 0; jp < 4; jp++) {
                    u32 kb0, kb1, kb2, kb3, kc0, kc1, kc2, kc3;
                    u32 off = swz(jp * 16 + brow0, 2 * ks + bchb);
                    ldsm4(kb0, kb1, kb2, kb3, bKh + off);
                    ldsm4(kc0, kc1, kc2, kc3, bKl + off);
                    mma16816(S[2 * jp],     qh[ks], kb0, kb1);
                    mma16816(S[2 * jp],     qh[ks], kc0, kc1);
                    mma16816(S[2 * jp],     ql[ks], kb0, kb1);
                    mma16816(S[2 * jp + 1], qh[ks], kb2, kb3);
                    mma16816(S[2 * jp + 1], qh[ks], kc2, kc3);
                    mma16816(S[2 * jp + 1], ql[ks], kb2, kb3);
                }
            }

            // ---- causal mask on diagonal block ----
            if (kb == qb) {
                const int rl0 = w * 16 + gid;
                const int rl1 = rl0 + 8;
#pragma unroll
                for (int j = 0; j < 8; j++) {
#pragma unroll
                    for (int e = 0; e < 2; e++) {
                        int col = 8 * j + 2 * tig + e;
                        if (col > rl0) S[j][e]     = -CUDART_INF_F;
                        if (col > rl1) S[j][2 + e] = -CUDART_INF_F;
                    }
                }
            }

            // ---- online softmax (rows gid, gid+8; 4 lanes per row) ----
            float mx0 = S[0][0], mx1 = S[0][2];
#pragma unroll
            for (int j = 0; j < 8; j++) {
                mx0 = fmaxf(mx0, fmaxf(S[j][0], S[j][1]));
                mx1 = fmaxf(mx1, fmaxf(S[j][2], S[j][3]));
            }
            mx0 = fmaxf(mx0, __shfl_xor_sync(0xffffffffu, mx0, 1));
            mx0 = fmaxf(mx0, __shfl_xor_sync(0xffffffffu, mx0, 2));
            mx1 = fmaxf(mx1, __shfl_xor_sync(0xffffffffu, mx1, 1));
            mx1 = fmaxf(mx1, __shfl_xor_sync(0xffffffffu, mx1, 2));
            const float mn0 = fmaxf(m0, mx0), mn1 = fmaxf(m1, mx1);
            const float corr0 = ex2f(m0 - mn0), corr1 = ex2f(m1 - mn1);
            m0 = mn0; m1 = mn1;
            float rs0 = 0.f, rs1 = 0.f;
#pragma unroll
            for (int j = 0; j < 8; j++) {
                S[j][0] = ex2f(S[j][0] - mn0); rs0 += S[j][0];
                S[j][1] = ex2f(S[j][1] - mn0); rs0 += S[j][1];
                S[j][2] = ex2f(S[j][2] - mn1); rs1 += S[j][2];
                S[j][3] = ex2f(S[j][3] - mn1); rs1 += S[j][3];
            }
            rs0 += __shfl_xor_sync(0xffffffffu, rs0, 1);
            rs0 += __shfl_xor_sync(0xffffffffu, rs0, 2);
            rs1 += __shfl_xor_sync(0xffffffffu, rs1, 1);
            rs1 += __shfl_xor_sync(0xffffffffu, rs1, 2);
            l0 = l0 * corr0 + rs0;
            l1 = l1 * corr1 + rs1;
#pragma unroll
            for (int j = 0; j < 8; j++) {
                O[j][0] *= corr0; O[j][1] *= corr0;
                O[j][2] *= corr1; O[j][3] *= corr1;
            }

            // ---- O += P V, 3-term bf16 split; P frags straight from S regs ----
#pragma unroll
            for (int ks = 0; ks < 4; ks++) {
                u32 ah[4], al[4];
                split2(S[2 * ks][0],     S[2 * ks][1],     ah[0], al[0]);
                split2(S[2 * ks][2],     S[2 * ks][3],     ah[1], al[1]);
                split2(S[2 * ks + 1][0], S[2 * ks + 1][1], ah[2], al[2]);
                split2(S[2 * ks + 1][2], S[2 * ks + 1][3], ah[3], al[3]);
#pragma unroll
                for (int jp = 0; jp < 4; jp++) {
                    u32 vb0, vb1, vb2, vb3, vc0, vc1, vc2, vc3;
                    u32 off = swz(jp * 16 + brow0, 2 * ks + bchb);
                    ldsm4(vb0, vb1, vb2, vb3, bVh + off);
                    ldsm4(vc0, vc1, vc2, vc3, bVl + off);
                    mma16816(O[2 * jp],     ah, vb0, vb1);
                    mma16816(O[2 * jp],     ah, vc0, vc1);
                    mma16816(O[2 * jp],     al, vb0, vb1);
                    mma16816(O[2 * jp + 1], ah, vb2, vb3);
                    mma16816(O[2 * jp + 1], ah, vc2, vc3);
                    mma16816(O[2 * jp + 1], al, vb2, vb3);
                }
            }
        }

        // ---- epilogue: normalize + store ----
        const float inv0 = 1.0f / l0;
        const float inv1 = 1.0f / l1;
        const size_t g0 = (size_t)(h * SQn + Q0 + w * 16 + gid) * Dn;
        const size_t g1 = g0 + (size_t)8 * Dn;
#pragma unroll
        for (int j = 0; j < 8; j++) {
            int col = 8 * j + 2 * tig;
            *(float2*)(Og + g0 + col) = make_float2(O[j][0] * inv0, O[j][1] * inv0);
            *(float2*)(Og + g1 + col) = make_float2(O[j][2] * inv1, O[j][3] * inv1);
        }
    }
}

extern "C" void kernel_launch(void* const* d_in, const int* in_sizes, int n_in,
                              void* d_out, int out_size)
{
    (void)in_sizes; (void)n_in; (void)out_size;
    const float* q = (const float*)d_in[0];
    const float* k = (const float*)d_in[1];
    const float* v = (const float*)d_in[2];
    float* o = (float*)d_out;

    cudaFuncSetAttribute(swa_mma_kernel,
                         cudaFuncAttributeMaxDynamicSharedMemorySize, SMEM_TOTAL);
    reset_ctr_kernel<<<1, 1>>>();
    prep_kernel<<<dim3(64, Hn), 256>>>(k, v);
    swa_mma_kernel<<<444, 128, SMEM_TOTAL>>>(q, o);
}